// round 12
// baseline (speedup 1.0000x reference)
#include <cuda_runtime.h>
#include <cuda_fp16.h>
#include <cstdint>

// ---------------------------------------------------------------------------
// Problem constants
// ---------------------------------------------------------------------------
#define BATCH   64
#define LAT     556
#define KDIM    150528          // 3*224*224
#define NV      5023
#define VM      3500
#define D3      15069           // NV*3
#define OUTROWS 7079            // 3500 + 3500 + 68 + 11

// GEMM1 tiling
#define BN      64
#define BK      32
#define NBLK    9               // ceil(556/64)
#define KSPLIT  336
#define KITER   14              // 336*14*32 = 150528
#define ASTRIDE 20              // u32 stride for smem tiles (conflict-free)
#define NPAD    576
#define PSTRIDE (BATCH * NPAD)  // 36864

// Operand scaling: W (~0.001) pre-scaled by 64; lo parts scaled by 2048.
#define BSCALE      64.f
#define LSCALE      2048.f
#define INV_LSCALE  (1.f / 2048.f)
#define INV_BSCALE  (1.f / 64.f)

// Scratch (device globals -- no allocation allowed)
__device__ __half  g_xh[BATCH * KDIM];
__device__ __half  g_xl[BATCH * KDIM];
__device__ float   g_part[KSPLIT * PSTRIDE];   // split-K partials (49.5 MB)
__device__ float   g_latent[BATCH * LAT];
__device__ float   g_vert0[BATCH * D3];
__device__ float   g_stats[BATCH * 64];        // [0..46] geom out, [48..56] sums
__device__ double  g_statsd[BATCH * 16];       // double R/scale/t/vmean

// ---------------------------------------------------------------------------
// Helpers
// ---------------------------------------------------------------------------
__device__ __forceinline__ uint32_t pack_h2(float a, float b) {
    __half2 p = __floats2half2_rn(a, b);
    return *reinterpret_cast<uint32_t*>(&p);
}

__device__ __forceinline__ void split_hs(float v, float& h, float& l) {
    float hf = __half2float(__float2half_rn(v));
    h = hf;
    l = (v - hf) * LSCALE;
}

__device__ __forceinline__ void mma16816(float* d,
                                         uint32_t a0, uint32_t a1, uint32_t a2, uint32_t a3,
                                         uint32_t b0, uint32_t b1) {
    asm volatile(
        "mma.sync.aligned.m16n8k16.row.col.f32.f16.f16.f32 "
        "{%0,%1,%2,%3}, {%4,%5,%6,%7}, {%8,%9}, {%0,%1,%2,%3};\n"
        : "+f"(d[0]), "+f"(d[1]), "+f"(d[2]), "+f"(d[3])
        : "r"(a0), "r"(a1), "r"(a2), "r"(a3), "r"(b0), "r"(b1));
}

__device__ void aa2mat_d(double ax, double ay, double az, double R[3][3]) {
    double th = sqrt(ax * ax + ay * ay + az * az);
    double inv = 1.0 / fmax(th, 1e-8);
    double ux = ax * inv, uy = ay * inv, uz = az * inv;
    double s = sin(th), c = cos(th), mc = 1.0 - c;
    double uu = ux * ux + uy * uy + uz * uz;
    R[0][0] = 1.0 + mc * (ux * ux - uu);
    R[0][1] = -s * uz + mc * ux * uy;
    R[0][2] = s * uy + mc * ux * uz;
    R[1][0] = s * uz + mc * ux * uy;
    R[1][1] = 1.0 + mc * (uy * uy - uu);
    R[1][2] = -s * ux + mc * uy * uz;
    R[2][0] = -s * uy + mc * ux * uz;
    R[2][1] = s * ux + mc * uy * uz;
    R[2][2] = 1.0 + mc * (uz * uz - uu);
}

__device__ __forceinline__ void xform_dd(const double R[3][3], double sc, const double tv[3],
                                         const double vm[3], const double* v, double* o) {
    double wx = v[0] - vm[0], wy = v[1] - vm[1], wz = v[2] - vm[2];
    o[0] = (wx * R[0][0] + wy * R[1][0] + wz * R[2][0]) * sc + tv[0];
    o[1] = (wx * R[0][1] + wy * R[1][1] + wz * R[2][1]) * sc + tv[1];
    o[2] = (wx * R[0][2] + wy * R[1][2] + wz * R[2][2]) * sc + tv[2];
}

__device__ __forceinline__ void cross3_d(const double* a, const double* b, double* o) {
    o[0] = a[1] * b[2] - a[2] * b[1];
    o[1] = a[2] * b[0] - a[0] * b[2];
    o[2] = a[0] * b[1] - a[1] * b[0];
}
__device__ __forceinline__ double dot3_d(const double* a, const double* b) {
    return a[0] * b[0] + a[1] * b[1] + a[2] * b[2];
}

// ---------------------------------------------------------------------------
// K0: pre-split x into half hi/lo (done ONCE, removes split work from gemm)
// ---------------------------------------------------------------------------
__global__ void xsplit_kernel(const float* __restrict__ x) {
    int idx = blockIdx.x * 256 + threadIdx.x;        // one per 4 floats
    const int tot4 = (BATCH * KDIM) / 4;
    if (idx < tot4) {
        float4 v = reinterpret_cast<const float4*>(x)[idx];
        float h0, l0, h1, l1, h2, l2, h3, l3;
        split_hs(v.x, h0, l0); split_hs(v.y, h1, l1);
        split_hs(v.z, h2, l2); split_hs(v.w, h3, l3);
        uint2 ph = make_uint2(pack_h2(h0, h1), pack_h2(h2, h3));
        uint2 pl = make_uint2(pack_h2(l0, l1), pack_h2(l2, l3));
        reinterpret_cast<uint2*>(g_xh)[idx] = ph;
        reinterpret_cast<uint2*>(g_xl)[idx] = pl;
    }
}

// ---------------------------------------------------------------------------
// K1: split-K GEMM partials: g_part[ks] = x[:, krange] @ W[krange, :]
// grid (NBLK, KSPLIT), block 256. Register-prefetch pipelined.
// ---------------------------------------------------------------------------
__global__ void __launch_bounds__(256) gemm1_kernel(const float* __restrict__ W) {
    __shared__ uint32_t Ah[64 * ASTRIDE], Al[64 * ASTRIDE];
    __shared__ uint32_t Bh[64 * ASTRIDE], Bl[64 * ASTRIDE];

    const int t = threadIdx.x;
    const int n0 = blockIdx.x * BN;
    const int k0 = blockIdx.y * (KITER * BK);

    const int warp = t >> 5, lane = t & 31;
    const int wm = warp & 3;
    const int wn = warp >> 2;
    const int g = lane >> 2, tg = lane & 3;

    float acch[4][4], accm[4][4], accl[4][4];
#pragma unroll
    for (int i = 0; i < 4; i++)
#pragma unroll
        for (int j = 0; j < 4; j++) { acch[i][j] = 0.f; accm[i][j] = 0.f; accl[i][j] = 0.f; }

    const int xr = t >> 2, xq = t & 3;
    const int wnl = t & 63, wkq = t >> 6;
    const int ng = n0 + wnl;
    const bool wvalid = (ng < LAT);

    const __half* xhp = g_xh + (size_t)xr * KDIM + k0 + xq * 8;
    const __half* xlp = g_xl + (size_t)xr * KDIM + k0 + xq * 8;
    const float*  wp0 = W + (size_t)(k0 + wkq * 8) * LAT + ng;

    // initial prefetch
    uint4 rxh = *reinterpret_cast<const uint4*>(xhp);
    uint4 rxl = *reinterpret_cast<const uint4*>(xlp);
    float wr[8];
#pragma unroll
    for (int i = 0; i < 8; i++) wr[i] = 0.f;
    if (wvalid) {
#pragma unroll
        for (int i = 0; i < 8; i++) wr[i] = wp0[(size_t)i * LAT] * BSCALE;
    }

    for (int it = 0; it < KITER; ++it) {
        // ---- store staged regs to smem ----
        *reinterpret_cast<uint4*>(&Ah[xr * ASTRIDE + xq * 4]) = rxh;
        *reinterpret_cast<uint4*>(&Al[xr * ASTRIDE + xq * 4]) = rxl;
        {
            uint4 bh, bl;
            float he, le, ho, lo;
            split_hs(wr[0], he, le); split_hs(wr[1], ho, lo);
            bh.x = pack_h2(he, ho); bl.x = pack_h2(le, lo);
            split_hs(wr[2], he, le); split_hs(wr[3], ho, lo);
            bh.y = pack_h2(he, ho); bl.y = pack_h2(le, lo);
            split_hs(wr[4], he, le); split_hs(wr[5], ho, lo);
            bh.z = pack_h2(he, ho); bl.z = pack_h2(le, lo);
            split_hs(wr[6], he, le); split_hs(wr[7], ho, lo);
            bh.w = pack_h2(he, ho); bl.w = pack_h2(le, lo);
            *reinterpret_cast<uint4*>(&Bh[wnl * ASTRIDE + wkq * 4]) = bh;
            *reinterpret_cast<uint4*>(&Bl[wnl * ASTRIDE + wkq * 4]) = bl;
        }
        __syncthreads();

        // ---- prefetch next tile (overlaps with MMAs below) ----
        if (it + 1 < KITER) {
            rxh = *reinterpret_cast<const uint4*>(xhp + (size_t)(it + 1) * BK);
            rxl = *reinterpret_cast<const uint4*>(xlp + (size_t)(it + 1) * BK);
            if (wvalid) {
                const float* wp = wp0 + (size_t)(it + 1) * BK * LAT;
#pragma unroll
                for (int i = 0; i < 8; i++) wr[i] = wp[(size_t)i * LAT] * BSCALE;
            }
        }

        // ---- MMAs ----
        const int m0 = wm * 16;
#pragma unroll
        for (int s = 0; s < 2; s++) {
            int ka = s * 8 + tg;
            uint32_t ah0 = Ah[(m0 + g) * ASTRIDE + ka];
            uint32_t ah1 = Ah[(m0 + g + 8) * ASTRIDE + ka];
            uint32_t ah2 = Ah[(m0 + g) * ASTRIDE + ka + 4];
            uint32_t ah3 = Ah[(m0 + g + 8) * ASTRIDE + ka + 4];
            uint32_t al0 = Al[(m0 + g) * ASTRIDE + ka];
            uint32_t al1 = Al[(m0 + g + 8) * ASTRIDE + ka];
            uint32_t al2 = Al[(m0 + g) * ASTRIDE + ka + 4];
            uint32_t al3 = Al[(m0 + g + 8) * ASTRIDE + ka + 4];
#pragma unroll
            for (int nt = 0; nt < 4; nt++) {
                int nrow = wn * 32 + nt * 8 + g;
                uint32_t bh0 = Bh[nrow * ASTRIDE + ka];
                uint32_t bh1 = Bh[nrow * ASTRIDE + ka + 4];
                uint32_t bl0 = Bl[nrow * ASTRIDE + ka];
                uint32_t bl1 = Bl[nrow * ASTRIDE + ka + 4];
                mma16816(acch[nt], ah0, ah1, ah2, ah3, bh0, bh1);
                mma16816(accm[nt], ah0, ah1, ah2, ah3, bl0, bl1);
                mma16816(accm[nt], al0, al1, al2, al3, bh0, bh1);
                mma16816(accl[nt], al0, al1, al2, al3, bl0, bl1);
            }
        }
        __syncthreads();
    }

    // ---- write fp32 partials (no atomics) ----
    float* pb = g_part + (size_t)blockIdx.y * PSTRIDE;
    const int mr0 = wm * 16 + g;
#pragma unroll
    for (int nt = 0; nt < 4; nt++) {
        int ncol = n0 + wn * 32 + nt * 8 + 2 * tg;
        float v00 = (acch[nt][0] + (accm[nt][0] + accl[nt][0] * INV_LSCALE) * INV_LSCALE) * INV_BSCALE;
        float v01 = (acch[nt][1] + (accm[nt][1] + accl[nt][1] * INV_LSCALE) * INV_LSCALE) * INV_BSCALE;
        float v10 = (acch[nt][2] + (accm[nt][2] + accl[nt][2] * INV_LSCALE) * INV_LSCALE) * INV_BSCALE;
        float v11 = (acch[nt][3] + (accm[nt][3] + accl[nt][3] * INV_LSCALE) * INV_LSCALE) * INV_BSCALE;
        *reinterpret_cast<float2*>(&pb[mr0 * NPAD + ncol]) = make_float2(v00, v01);
        *reinterpret_cast<float2*>(&pb[(mr0 + 8) * NPAD + ncol]) = make_float2(v10, v11);
    }
}

// ---------------------------------------------------------------------------
// K2: latent[m][n] = bias[n] + sum_ks part[ks][m][n]  (exact double tree)
// grid 64 (m), block 576 (n)
// ---------------------------------------------------------------------------
__global__ void __launch_bounds__(NPAD) reduce_kernel(const float* __restrict__ enc_b) {
    const int m = blockIdx.x;
    const int n = threadIdx.x;
    if (n >= LAT) return;
    double s = (double)enc_b[n];
    const float* p = g_part + m * NPAD + n;
#pragma unroll 8
    for (int ks = 0; ks < KSPLIT; ks++)
        s += (double)p[(size_t)ks * PSTRIDE];
    g_latent[m * LAT + n] = (float)s;
}

// ---------------------------------------------------------------------------
// K3: vert0 = template + shape_p @ shape_basis
// grid (118, 2), block 128; thread owns one j-column, 32 batches
// ---------------------------------------------------------------------------
__global__ void __launch_bounds__(128) shape_kernel(const float* __restrict__ basis,
                                                    const float* __restrict__ vtempl) {
    __shared__ float sp[100 * 32];  // [k][b]
    const int t = threadIdx.x;
    const int bh = blockIdx.y * 32;

    int j = blockIdx.x * 128 + t;
    int jc = j < D3 ? j : D3 - 1;

    float accv[32];
#pragma unroll
    for (int b = 0; b < 32; b++) accv[b] = 0.f;

    for (int chunk = 0; chunk < 4; chunk++) {
        const int k0 = chunk * 100;
        for (int i = t; i < 100 * 32; i += 128) {
            int k = i >> 5, bb = i & 31;
            sp[i] = g_latent[(bh + bb) * LAT + k0 + k];
        }
        __syncthreads();

        const float* bp = basis + (size_t)k0 * D3 + jc;
        for (int k = 0; k < 100; k++) {
            float bs = bp[(size_t)k * D3];
            const float4* s4 = (const float4*)(sp + k * 32);
#pragma unroll
            for (int q = 0; q < 8; q++) {
                float4 sv = s4[q];
                accv[4 * q + 0] = fmaf(sv.x, bs, accv[4 * q + 0]);
                accv[4 * q + 1] = fmaf(sv.y, bs, accv[4 * q + 1]);
                accv[4 * q + 2] = fmaf(sv.z, bs, accv[4 * q + 2]);
                accv[4 * q + 3] = fmaf(sv.w, bs, accv[4 * q + 3]);
            }
        }
        __syncthreads();
    }

    if (j < D3) {
        float tmpl = vtempl[j];
#pragma unroll
        for (int b = 0; b < 32; b++)
            g_vert0[(size_t)(bh + b) * D3 + j] = tmpl + accv[b];
    }
}

// ---------------------------------------------------------------------------
// K4: per-batch vertex sums (vmean + eye means), grid 64, block 256
// ---------------------------------------------------------------------------
__global__ void stats_kernel() {
    const int b = blockIdx.x, t = threadIdx.x;
    __shared__ float red[9][256];

    float s[9];
#pragma unroll
    for (int i = 0; i < 9; i++) s[i] = 0.f;

    const float* vb = g_vert0 + (size_t)b * D3;
    for (int v = t; v < NV; v += 256) {
        float px = vb[v * 3], py = vb[v * 3 + 1], pz = vb[v * 3 + 2];
        s[0] += px; s[1] += py; s[2] += pz;
        if (v >= 3931) {
            if (v < 4477) { s[3] += px; s[4] += py; s[5] += pz; }
            else          { s[6] += px; s[7] += py; s[8] += pz; }
        }
    }
#pragma unroll
    for (int i = 0; i < 9; i++) red[i][t] = s[i];
    __syncthreads();
    for (int o = 128; o > 0; o >>= 1) {
        if (t < o)
#pragma unroll
            for (int i = 0; i < 9; i++) red[i][t] += red[i][t + o];
        __syncthreads();
    }
    if (t == 0) {
#pragma unroll
        for (int i = 0; i < 9; i++) g_stats[b * 64 + 48 + i] = red[i][0];
    }
}

// ---------------------------------------------------------------------------
// K5: scalar geometry per batch (double), 1 block x 64 threads
// NOTE: eyeball vertex rotations are dead code (written but never read);
// only eye-centre means matter, and means commute with the affine transform.
// ---------------------------------------------------------------------------
__global__ void geom_kernel(const int* __restrict__ landmarks) {
    const int b = threadIdx.x;
    if (b >= BATCH) return;

    float* st = g_stats + b * 64;
    double* sd = g_statsd + b * 16;
    const float* lat = g_latent + b * LAT;
    const float* vb = g_vert0 + (size_t)b * D3;

    double vm[3], lm[3], rm[3];
#pragma unroll
    for (int i = 0; i < 3; i++) {
        vm[i] = (double)st[48 + i] / (double)NV;
        lm[i] = (double)st[51 + i] / 546.0;
        rm[i] = (double)st[54 + i] / 546.0;
    }

    // three independent Rodrigues (ILP)
    double R[3][3], Rl[3][3], Rr[3][3];
    aa2mat_d((double)lat[545], (double)lat[546], (double)lat[547], R);
    aa2mat_d((double)lat[552], (double)lat[553], 0.0, Rl);
    aa2mat_d((double)lat[554], (double)lat[555], 0.0, Rr);

    double scale = (double)lat[551] + 1.0;
    double tv[3] = {(double)lat[548], (double)lat[549], (double)lat[550]};

    // publish transform (double + float copies)
#pragma unroll
    for (int r = 0; r < 3; r++)
#pragma unroll
        for (int c = 0; c < 3; c++) { sd[r * 3 + c] = R[r][c]; st[r * 3 + c] = (float)R[r][c]; }
    sd[9] = scale; st[9] = (float)scale;
#pragma unroll
    for (int c = 0; c < 3; c++) {
        sd[10 + c] = tv[c]; st[10 + c] = (float)tv[c];
        sd[13 + c] = vm[c]; st[13 + c] = (float)vm[c];
    }

    double lc[3], rc[3];
    xform_dd(R, scale, tv, vm, lm, lc);
    xform_dd(R, scale, tv, vm, rm, rc);

    int i4[4] = {landmarks[19], landmarks[22], landmarks[25], landmarks[28]};
    int i2[2] = {landmarks[14], landmarks[18]};
    double fcr[3];
#pragma unroll
    for (int c = 0; c < 3; c++) {
        double m4 = 0.0, m2 = 0.0;
#pragma unroll
        for (int q = 0; q < 4; q++) m4 += (double)vb[i4[q] * 3 + c];
#pragma unroll
        for (int q = 0; q < 2; q++) m2 += (double)vb[i2[q] * 3 + c];
        fcr[c] = (m4 * 0.25 + m2 * 0.5) * 0.5;
    }
    double fc[3];
    xform_dd(R, scale, tv, vm, fcr, fc);

    // gaze vectors: (0,0,-1) @ R_rot = -(row 2)
    double lg[3] = {-Rl[2][0], -Rl[2][1], -Rl[2][2]};
    double rg[3] = {-Rr[2][0], -Rr[2][1], -Rr[2][2]};
    double cr[3];
    cross3_d(rg, lg, cr);

    double c1[3] = {-rg[0], -rg[1], -rg[2]};
    double rhs[3] = {rc[0] - lc[0], rc[1] - lc[1], rc[2] - lc[2]};
    double c1xc2[3], rhsxc2[3];
    cross3_d(c1, cr, c1xc2);
    cross3_d(rhs, cr, rhsxc2);
    double det = dot3_d(lg, c1xc2);
    double inv = 1.0 / det;
    double sol0 = dot3_d(rhs, c1xc2) * inv;
    double sol1 = dot3_d(lg, rhsxc2) * inv;

    double gpl[3], gpr[3], gpm[3];
#pragma unroll
    for (int c = 0; c < 3; c++) {
        gpl[c] = lc[c] + sol0 * lg[c];
        gpr[c] = rc[c] + sol1 * rg[c];
        gpm[c] = 0.5 * (gpl[c] + gpr[c]);
    }
    double dd[3] = {gpl[0] - gpr[0], gpl[1] - gpr[1], gpl[2] - gpr[2]};
    double dist = sqrt(dot3_d(dd, dd));

#pragma unroll
    for (int c = 0; c < 3; c++) {
        st[16 + c] = (float)lc[c];
        st[19 + c] = (float)rc[c];
        st[22 + c] = (float)fc[c];
        st[25 + c] = (float)gpl[c];
        st[28 + c] = (float)gpr[c];
        st[31 + c] = (float)gpm[c];
        st[34 + c] = (float)(lc[c] + lg[c] * 1000.0);
        st[37 + c] = (float)(rc[c] + rg[c] * 1000.0);
        st[40 + c] = (float)lg[c];
        st[43 + c] = (float)rg[c];
    }
    st[46] = (float)dist;
}

// ---------------------------------------------------------------------------
// K6: output assembly (vertex chain in double to kill z-amplified error)
// grid (28, 64), block 128
// ---------------------------------------------------------------------------
__global__ void out_kernel(const float* __restrict__ cam,
                           const int* __restrict__ mlm,
                           float* __restrict__ out) {
    const int b = blockIdx.y;
    const int r = blockIdx.x * 128 + threadIdx.x;
    const float* st = g_stats + b * 64;
    const double* sd = g_statsd + b * 16;
    const float* vb = g_vert0 + (size_t)b * D3;
    float* ob = out + (size_t)b * OUTROWS * 3;

    if (r < 3500) {
        double vx = (double)vb[r * 3], vy = (double)vb[r * 3 + 1], vz = (double)vb[r * 3 + 2];
        double wx = vx - sd[13], wy = vy - sd[14], wz = vz - sd[15];
        double sc = sd[9];
        double ox = (wx * sd[0] + wy * sd[3] + wz * sd[6]) * sc + sd[10];
        double oy = (wx * sd[1] + wy * sd[4] + wz * sd[7]) * sc + sd[11];
        double oz = (wx * sd[2] + wy * sd[5] + wz * sd[8]) * sc + sd[12];
        ob[r * 3] = (float)ox; ob[r * 3 + 1] = (float)oy; ob[r * 3 + 2] = (float)oz;

        const float* C = cam + b * 12;
        double p0 = (double)C[0] * ox + (double)C[1] * oy + (double)C[2] * oz + (double)C[3];
        double p1 = (double)C[4] * ox + (double)C[5] * oy + (double)C[6] * oz + (double)C[7];
        double p2 = (double)C[8] * ox + (double)C[9] * oy + (double)C[10] * oz + (double)C[11];
        double zs = (p2 >= 0.0 ? 1.0 : -1.0) * fmax(fabs(p2), 0.001);
        size_t o2 = (size_t)(3500 + r) * 3;
        ob[o2] = __fdiv_rn((float)p0, (float)zs);
        ob[o2 + 1] = __fdiv_rn((float)p1, (float)zs);
        ob[o2 + 2] = (float)p2;
    } else if (r < 3568) {
        int i = r - 3500;
        int vi = mlm[i];
        double vx = (double)vb[vi * 3], vy = (double)vb[vi * 3 + 1], vz = (double)vb[vi * 3 + 2];
        double wx = vx - sd[13], wy = vy - sd[14], wz = vz - sd[15];
        double sc = sd[9];
        size_t o = (size_t)(7000 + i) * 3;
        ob[o]     = (float)((wx * sd[0] + wy * sd[3] + wz * sd[6]) * sc + sd[10]);
        ob[o + 1] = (float)((wx * sd[1] + wy * sd[4] + wz * sd[7]) * sc + sd[11]);
        ob[o + 2] = (float)((wx * sd[2] + wy * sd[5] + wz * sd[8]) * sc + sd[12]);
    } else if (r < 3578) {
        int sidx = r - 3568;
        size_t o = (size_t)(7068 + sidx) * 3;
        ob[o] = st[16 + 3 * sidx];
        ob[o + 1] = st[17 + 3 * sidx];
        ob[o + 2] = st[18 + 3 * sidx];
    } else if (r == 3578) {
        float d = st[46];
        size_t o = (size_t)7078 * 3;
        ob[o] = d; ob[o + 1] = d; ob[o + 2] = d;
    }
}

// ---------------------------------------------------------------------------
// Launch
// ---------------------------------------------------------------------------
extern "C" void kernel_launch(void* const* d_in, const int* in_sizes, int n_in,
                              void* d_out, int out_size) {
    const float* x      = (const float*)d_in[0];
    const float* enc_W  = (const float*)d_in[1];
    const float* enc_b  = (const float*)d_in[2];
    const float* vtempl = (const float*)d_in[3];
    const float* basis  = (const float*)d_in[4];
    const float* cam    = (const float*)d_in[5];
    const int* landmarks = (const int*)d_in[6];
    const int* mlm       = (const int*)d_in[7];
    float* out = (float*)d_out;

    xsplit_kernel<<<(BATCH * KDIM / 4 + 255) / 256, 256>>>(x);
    gemm1_kernel<<<dim3(NBLK, KSPLIT), 256>>>(enc_W);
    reduce_kernel<<<BATCH, NPAD>>>(enc_b);
    shape_kernel<<<dim3(118, 2), 128>>>(basis, vtempl);
    stats_kernel<<<BATCH, 256>>>();
    geom_kernel<<<1, 64>>>(landmarks);
    out_kernel<<<dim3(28, BATCH), 128>>>(cam, mlm, out);
}

// round 13
// speedup vs baseline: 1.0013x; 1.0013x over previous
#include <cuda_runtime.h>
#include <cuda_fp16.h>
#include <cstdint>

// ---------------------------------------------------------------------------
// Problem constants
// ---------------------------------------------------------------------------
#define BATCH   64
#define LAT     556
#define KDIM    150528          // 3*224*224
#define NV      5023
#define VM      3500
#define D3      15069           // NV*3
#define OUTROWS 7079            // 3500 + 3500 + 68 + 11

// GEMM1 tiling
#define BN      64
#define BK      32
#define NBLK    9               // ceil(556/64)
#define KSPLIT  336
#define KITER   14              // 336*14*32 = 150528
#define ASTRIDE 20              // u32 stride for smem tiles (conflict-free)
#define NPAD    576
#define PSTRIDE (BATCH * NPAD)  // 36864

// Operand scaling: W (~0.001) pre-scaled by 64; lo parts scaled by 2048.
#define BSCALE      64.f
#define LSCALE      2048.f
#define INV_LSCALE  (1.f / 2048.f)
#define INV_BSCALE  (1.f / 64.f)

// Scratch (device globals -- no allocation allowed)
__device__ __half  g_xh[BATCH * KDIM];
__device__ __half  g_xl[BATCH * KDIM];
__device__ float   g_part[KSPLIT * PSTRIDE];   // split-K partials (49.5 MB)
__device__ float   g_latent[BATCH * LAT];
__device__ float   g_vert0[BATCH * D3];
__device__ float   g_stats[BATCH * 64];        // [0..46] geom out, [48..56] sums
__device__ double  g_statsd[BATCH * 16];       // double R/scale/t/vmean

// ---------------------------------------------------------------------------
// Helpers
// ---------------------------------------------------------------------------
__device__ __forceinline__ uint32_t pack_h2(float a, float b) {
    __half2 p = __floats2half2_rn(a, b);
    return *reinterpret_cast<uint32_t*>(&p);
}

__device__ __forceinline__ void split_hs(float v, float& h, float& l) {
    float hf = __half2float(__float2half_rn(v));
    h = hf;
    l = (v - hf) * LSCALE;
}

__device__ __forceinline__ void mma16816(float* d,
                                         uint32_t a0, uint32_t a1, uint32_t a2, uint32_t a3,
                                         uint32_t b0, uint32_t b1) {
    asm volatile(
        "mma.sync.aligned.m16n8k16.row.col.f32.f16.f16.f32 "
        "{%0,%1,%2,%3}, {%4,%5,%6,%7}, {%8,%9}, {%0,%1,%2,%3};\n"
        : "+f"(d[0]), "+f"(d[1]), "+f"(d[2]), "+f"(d[3])
        : "r"(a0), "r"(a1), "r"(a2), "r"(a3), "r"(b0), "r"(b1));
}

__device__ void aa2mat_d(double ax, double ay, double az, double R[3][3]) {
    double th = sqrt(ax * ax + ay * ay + az * az);
    double inv = 1.0 / fmax(th, 1e-8);
    double ux = ax * inv, uy = ay * inv, uz = az * inv;
    double s = sin(th), c = cos(th), mc = 1.0 - c;
    double uu = ux * ux + uy * uy + uz * uz;
    R[0][0] = 1.0 + mc * (ux * ux - uu);
    R[0][1] = -s * uz + mc * ux * uy;
    R[0][2] = s * uy + mc * ux * uz;
    R[1][0] = s * uz + mc * ux * uy;
    R[1][1] = 1.0 + mc * (uy * uy - uu);
    R[1][2] = -s * ux + mc * uy * uz;
    R[2][0] = -s * uy + mc * ux * uz;
    R[2][1] = s * ux + mc * uy * uz;
    R[2][2] = 1.0 + mc * (uz * uz - uu);
}

__device__ __forceinline__ void xform_dd(const double R[3][3], double sc, const double tv[3],
                                         const double vm[3], const double* v, double* o) {
    double wx = v[0] - vm[0], wy = v[1] - vm[1], wz = v[2] - vm[2];
    o[0] = (wx * R[0][0] + wy * R[1][0] + wz * R[2][0]) * sc + tv[0];
    o[1] = (wx * R[0][1] + wy * R[1][1] + wz * R[2][1]) * sc + tv[1];
    o[2] = (wx * R[0][2] + wy * R[1][2] + wz * R[2][2]) * sc + tv[2];
}

__device__ __forceinline__ void cross3_d(const double* a, const double* b, double* o) {
    o[0] = a[1] * b[2] - a[2] * b[1];
    o[1] = a[2] * b[0] - a[0] * b[2];
    o[2] = a[0] * b[1] - a[1] * b[0];
}
__device__ __forceinline__ double dot3_d(const double* a, const double* b) {
    return a[0] * b[0] + a[1] * b[1] + a[2] * b[2];
}

// ---------------------------------------------------------------------------
// K0: pre-split x into half hi/lo (done ONCE, removes split work from gemm)
// ---------------------------------------------------------------------------
__global__ void xsplit_kernel(const float* __restrict__ x) {
    int idx = blockIdx.x * 256 + threadIdx.x;        // one per 4 floats
    const int tot4 = (BATCH * KDIM) / 4;
    if (idx < tot4) {
        float4 v = reinterpret_cast<const float4*>(x)[idx];
        float h0, l0, h1, l1, h2, l2, h3, l3;
        split_hs(v.x, h0, l0); split_hs(v.y, h1, l1);
        split_hs(v.z, h2, l2); split_hs(v.w, h3, l3);
        uint2 ph = make_uint2(pack_h2(h0, h1), pack_h2(h2, h3));
        uint2 pl = make_uint2(pack_h2(l0, l1), pack_h2(l2, l3));
        reinterpret_cast<uint2*>(g_xh)[idx] = ph;
        reinterpret_cast<uint2*>(g_xl)[idx] = pl;
    }
}

// ---------------------------------------------------------------------------
// K1: split-K GEMM partials: g_part[ks] = x[:, krange] @ W[krange, :]
// grid (NBLK, KSPLIT), block 256. Register-prefetch pipelined.
// ---------------------------------------------------------------------------
__global__ void __launch_bounds__(256) gemm1_kernel(const float* __restrict__ W) {
    __shared__ uint32_t Ah[64 * ASTRIDE], Al[64 * ASTRIDE];
    __shared__ uint32_t Bh[64 * ASTRIDE], Bl[64 * ASTRIDE];

    const int t = threadIdx.x;
    const int n0 = blockIdx.x * BN;
    const int k0 = blockIdx.y * (KITER * BK);

    const int warp = t >> 5, lane = t & 31;
    const int wm = warp & 3;
    const int wn = warp >> 2;
    const int g = lane >> 2, tg = lane & 3;

    float acch[4][4], accm[4][4], accl[4][4];
#pragma unroll
    for (int i = 0; i < 4; i++)
#pragma unroll
        for (int j = 0; j < 4; j++) { acch[i][j] = 0.f; accm[i][j] = 0.f; accl[i][j] = 0.f; }

    const int xr = t >> 2, xq = t & 3;
    const int wnl = t & 63, wkq = t >> 6;
    const int ng = n0 + wnl;
    const bool wvalid = (ng < LAT);

    const __half* xhp = g_xh + (size_t)xr * KDIM + k0 + xq * 8;
    const __half* xlp = g_xl + (size_t)xr * KDIM + k0 + xq * 8;
    const float*  wp0 = W + (size_t)(k0 + wkq * 8) * LAT + ng;

    // initial prefetch
    uint4 rxh = *reinterpret_cast<const uint4*>(xhp);
    uint4 rxl = *reinterpret_cast<const uint4*>(xlp);
    float wr[8];
#pragma unroll
    for (int i = 0; i < 8; i++) wr[i] = 0.f;
    if (wvalid) {
#pragma unroll
        for (int i = 0; i < 8; i++) wr[i] = wp0[(size_t)i * LAT] * BSCALE;
    }

    for (int it = 0; it < KITER; ++it) {
        // ---- store staged regs to smem ----
        *reinterpret_cast<uint4*>(&Ah[xr * ASTRIDE + xq * 4]) = rxh;
        *reinterpret_cast<uint4*>(&Al[xr * ASTRIDE + xq * 4]) = rxl;
        {
            uint4 bh, bl;
            float he, le, ho, lo;
            split_hs(wr[0], he, le); split_hs(wr[1], ho, lo);
            bh.x = pack_h2(he, ho); bl.x = pack_h2(le, lo);
            split_hs(wr[2], he, le); split_hs(wr[3], ho, lo);
            bh.y = pack_h2(he, ho); bl.y = pack_h2(le, lo);
            split_hs(wr[4], he, le); split_hs(wr[5], ho, lo);
            bh.z = pack_h2(he, ho); bl.z = pack_h2(le, lo);
            split_hs(wr[6], he, le); split_hs(wr[7], ho, lo);
            bh.w = pack_h2(he, ho); bl.w = pack_h2(le, lo);
            *reinterpret_cast<uint4*>(&Bh[wnl * ASTRIDE + wkq * 4]) = bh;
            *reinterpret_cast<uint4*>(&Bl[wnl * ASTRIDE + wkq * 4]) = bl;
        }
        __syncthreads();

        // ---- prefetch next tile (overlaps with MMAs below) ----
        if (it + 1 < KITER) {
            rxh = *reinterpret_cast<const uint4*>(xhp + (size_t)(it + 1) * BK);
            rxl = *reinterpret_cast<const uint4*>(xlp + (size_t)(it + 1) * BK);
            if (wvalid) {
                const float* wp = wp0 + (size_t)(it + 1) * BK * LAT;
#pragma unroll
                for (int i = 0; i < 8; i++) wr[i] = wp[(size_t)i * LAT] * BSCALE;
            }
        }

        // ---- MMAs ----
        const int m0 = wm * 16;
#pragma unroll
        for (int s = 0; s < 2; s++) {
            int ka = s * 8 + tg;
            uint32_t ah0 = Ah[(m0 + g) * ASTRIDE + ka];
            uint32_t ah1 = Ah[(m0 + g + 8) * ASTRIDE + ka];
            uint32_t ah2 = Ah[(m0 + g) * ASTRIDE + ka + 4];
            uint32_t ah3 = Ah[(m0 + g + 8) * ASTRIDE + ka + 4];
            uint32_t al0 = Al[(m0 + g) * ASTRIDE + ka];
            uint32_t al1 = Al[(m0 + g + 8) * ASTRIDE + ka];
            uint32_t al2 = Al[(m0 + g) * ASTRIDE + ka + 4];
            uint32_t al3 = Al[(m0 + g + 8) * ASTRIDE + ka + 4];
#pragma unroll
            for (int nt = 0; nt < 4; nt++) {
                int nrow = wn * 32 + nt * 8 + g;
                uint32_t bh0 = Bh[nrow * ASTRIDE + ka];
                uint32_t bh1 = Bh[nrow * ASTRIDE + ka + 4];
                uint32_t bl0 = Bl[nrow * ASTRIDE + ka];
                uint32_t bl1 = Bl[nrow * ASTRIDE + ka + 4];
                mma16816(acch[nt], ah0, ah1, ah2, ah3, bh0, bh1);
                mma16816(accm[nt], ah0, ah1, ah2, ah3, bl0, bl1);
                mma16816(accm[nt], al0, al1, al2, al3, bh0, bh1);
                mma16816(accl[nt], al0, al1, al2, al3, bl0, bl1);
            }
        }
        __syncthreads();
    }

    // ---- write fp32 partials (no atomics) ----
    float* pb = g_part + (size_t)blockIdx.y * PSTRIDE;
    const int mr0 = wm * 16 + g;
#pragma unroll
    for (int nt = 0; nt < 4; nt++) {
        int ncol = n0 + wn * 32 + nt * 8 + 2 * tg;
        float v00 = (acch[nt][0] + (accm[nt][0] + accl[nt][0] * INV_LSCALE) * INV_LSCALE) * INV_BSCALE;
        float v01 = (acch[nt][1] + (accm[nt][1] + accl[nt][1] * INV_LSCALE) * INV_LSCALE) * INV_BSCALE;
        float v10 = (acch[nt][2] + (accm[nt][2] + accl[nt][2] * INV_LSCALE) * INV_LSCALE) * INV_BSCALE;
        float v11 = (acch[nt][3] + (accm[nt][3] + accl[nt][3] * INV_LSCALE) * INV_LSCALE) * INV_BSCALE;
        *reinterpret_cast<float2*>(&pb[mr0 * NPAD + ncol]) = make_float2(v00, v01);
        *reinterpret_cast<float2*>(&pb[(mr0 + 8) * NPAD + ncol]) = make_float2(v10, v11);
    }
}

// ---------------------------------------------------------------------------
// K2: latent[m][n] = bias[n] + sum_ks part[ks][m][n]  (exact double tree)
// grid 64 (m), block 576 (n)
// ---------------------------------------------------------------------------
__global__ void __launch_bounds__(NPAD) reduce_kernel(const float* __restrict__ enc_b) {
    const int m = blockIdx.x;
    const int n = threadIdx.x;
    if (n >= LAT) return;
    double s = (double)enc_b[n];
    const float* p = g_part + m * NPAD + n;
#pragma unroll 8
    for (int ks = 0; ks < KSPLIT; ks++)
        s += (double)p[(size_t)ks * PSTRIDE];
    g_latent[m * LAT + n] = (float)s;
}

// ---------------------------------------------------------------------------
// K3: vert0 = template + shape_p @ shape_basis
// grid (118, 2), block 128; thread owns one j-column, 32 batches
// ---------------------------------------------------------------------------
__global__ void __launch_bounds__(128) shape_kernel(const float* __restrict__ basis,
                                                    const float* __restrict__ vtempl) {
    __shared__ float sp[100 * 32];  // [k][b]
    const int t = threadIdx.x;
    const int bh = blockIdx.y * 32;

    int j = blockIdx.x * 128 + t;
    int jc = j < D3 ? j : D3 - 1;

    float accv[32];
#pragma unroll
    for (int b = 0; b < 32; b++) accv[b] = 0.f;

    for (int chunk = 0; chunk < 4; chunk++) {
        const int k0 = chunk * 100;
        for (int i = t; i < 100 * 32; i += 128) {
            int k = i >> 5, bb = i & 31;
            sp[i] = g_latent[(bh + bb) * LAT + k0 + k];
        }
        __syncthreads();

        const float* bp = basis + (size_t)k0 * D3 + jc;
        for (int k = 0; k < 100; k++) {
            float bs = bp[(size_t)k * D3];
            const float4* s4 = (const float4*)(sp + k * 32);
#pragma unroll
            for (int q = 0; q < 8; q++) {
                float4 sv = s4[q];
                accv[4 * q + 0] = fmaf(sv.x, bs, accv[4 * q + 0]);
                accv[4 * q + 1] = fmaf(sv.y, bs, accv[4 * q + 1]);
                accv[4 * q + 2] = fmaf(sv.z, bs, accv[4 * q + 2]);
                accv[4 * q + 3] = fmaf(sv.w, bs, accv[4 * q + 3]);
            }
        }
        __syncthreads();
    }

    if (j < D3) {
        float tmpl = vtempl[j];
#pragma unroll
        for (int b = 0; b < 32; b++)
            g_vert0[(size_t)(bh + b) * D3 + j] = tmpl + accv[b];
    }
}

// ---------------------------------------------------------------------------
// K4: per-batch vertex sums (vmean + eye means), grid 64, block 256
// ---------------------------------------------------------------------------
__global__ void stats_kernel() {
    const int b = blockIdx.x, t = threadIdx.x;
    __shared__ float red[9][256];

    float s[9];
#pragma unroll
    for (int i = 0; i < 9; i++) s[i] = 0.f;

    const float* vb = g_vert0 + (size_t)b * D3;
    for (int v = t; v < NV; v += 256) {
        float px = vb[v * 3], py = vb[v * 3 + 1], pz = vb[v * 3 + 2];
        s[0] += px; s[1] += py; s[2] += pz;
        if (v >= 3931) {
            if (v < 4477) { s[3] += px; s[4] += py; s[5] += pz; }
            else          { s[6] += px; s[7] += py; s[8] += pz; }
        }
    }
#pragma unroll
    for (int i = 0; i < 9; i++) red[i][t] = s[i];
    __syncthreads();
    for (int o = 128; o > 0; o >>= 1) {
        if (t < o)
#pragma unroll
            for (int i = 0; i < 9; i++) red[i][t] += red[i][t + o];
        __syncthreads();
    }
    if (t == 0) {
#pragma unroll
        for (int i = 0; i < 9; i++) g_stats[b * 64 + 48 + i] = red[i][0];
    }
}

// ---------------------------------------------------------------------------
// K5: scalar geometry per batch (double), 1 block x 64 threads
// NOTE: eyeball vertex rotations are dead code (written but never read);
// only eye-centre means matter, and means commute with the affine transform.
// ---------------------------------------------------------------------------
__global__ void geom_kernel(const int* __restrict__ landmarks) {
    const int b = threadIdx.x;
    if (b >= BATCH) return;

    float* st = g_stats + b * 64;
    double* sd = g_statsd + b * 16;
    const float* lat = g_latent + b * LAT;
    const float* vb = g_vert0 + (size_t)b * D3;

    double vm[3], lm[3], rm[3];
#pragma unroll
    for (int i = 0; i < 3; i++) {
        vm[i] = (double)st[48 + i] / (double)NV;
        lm[i] = (double)st[51 + i] / 546.0;
        rm[i] = (double)st[54 + i] / 546.0;
    }

    // three independent Rodrigues (ILP)
    double R[3][3], Rl[3][3], Rr[3][3];
    aa2mat_d((double)lat[545], (double)lat[546], (double)lat[547], R);
    aa2mat_d((double)lat[552], (double)lat[553], 0.0, Rl);
    aa2mat_d((double)lat[554], (double)lat[555], 0.0, Rr);

    double scale = (double)lat[551] + 1.0;
    double tv[3] = {(double)lat[548], (double)lat[549], (double)lat[550]};

    // publish transform (double + float copies)
#pragma unroll
    for (int r = 0; r < 3; r++)
#pragma unroll
        for (int c = 0; c < 3; c++) { sd[r * 3 + c] = R[r][c]; st[r * 3 + c] = (float)R[r][c]; }
    sd[9] = scale; st[9] = (float)scale;
#pragma unroll
    for (int c = 0; c < 3; c++) {
        sd[10 + c] = tv[c]; st[10 + c] = (float)tv[c];
        sd[13 + c] = vm[c]; st[13 + c] = (float)vm[c];
    }

    double lc[3], rc[3];
    xform_dd(R, scale, tv, vm, lm, lc);
    xform_dd(R, scale, tv, vm, rm, rc);

    int i4[4] = {landmarks[19], landmarks[22], landmarks[25], landmarks[28]};
    int i2[2] = {landmarks[14], landmarks[18]};
    double fcr[3];
#pragma unroll
    for (int c = 0; c < 3; c++) {
        double m4 = 0.0, m2 = 0.0;
#pragma unroll
        for (int q = 0; q < 4; q++) m4 += (double)vb[i4[q] * 3 + c];
#pragma unroll
        for (int q = 0; q < 2; q++) m2 += (double)vb[i2[q] * 3 + c];
        fcr[c] = (m4 * 0.25 + m2 * 0.5) * 0.5;
    }
    double fc[3];
    xform_dd(R, scale, tv, vm, fcr, fc);

    // gaze vectors: (0,0,-1) @ R_rot = -(row 2)
    double lg[3] = {-Rl[2][0], -Rl[2][1], -Rl[2][2]};
    double rg[3] = {-Rr[2][0], -Rr[2][1], -Rr[2][2]};
    double cr[3];
    cross3_d(rg, lg, cr);

    double c1[3] = {-rg[0], -rg[1], -rg[2]};
    double rhs[3] = {rc[0] - lc[0], rc[1] - lc[1], rc[2] - lc[2]};
    double c1xc2[3], rhsxc2[3];
    cross3_d(c1, cr, c1xc2);
    cross3_d(rhs, cr, rhsxc2);
    double det = dot3_d(lg, c1xc2);
    double inv = 1.0 / det;
    double sol0 = dot3_d(rhs, c1xc2) * inv;
    double sol1 = dot3_d(lg, rhsxc2) * inv;

    double gpl[3], gpr[3], gpm[3];
#pragma unroll
    for (int c = 0; c < 3; c++) {
        gpl[c] = lc[c] + sol0 * lg[c];
        gpr[c] = rc[c] + sol1 * rg[c];
        gpm[c] = 0.5 * (gpl[c] + gpr[c]);
    }
    double dd[3] = {gpl[0] - gpr[0], gpl[1] - gpr[1], gpl[2] - gpr[2]};
    double dist = sqrt(dot3_d(dd, dd));

#pragma unroll
    for (int c = 0; c < 3; c++) {
        st[16 + c] = (float)lc[c];
        st[19 + c] = (float)rc[c];
        st[22 + c] = (float)fc[c];
        st[25 + c] = (float)gpl[c];
        st[28 + c] = (float)gpr[c];
        st[31 + c] = (float)gpm[c];
        st[34 + c] = (float)(lc[c] + lg[c] * 1000.0);
        st[37 + c] = (float)(rc[c] + rg[c] * 1000.0);
        st[40 + c] = (float)lg[c];
        st[43 + c] = (float)rg[c];
    }
    st[46] = (float)dist;
}

// ---------------------------------------------------------------------------
// K6: output assembly (vertex chain in double to kill z-amplified error)
// grid (28, 64), block 128
// ---------------------------------------------------------------------------
__global__ void out_kernel(const float* __restrict__ cam,
                           const int* __restrict__ mlm,
                           float* __restrict__ out) {
    const int b = blockIdx.y;
    const int r = blockIdx.x * 128 + threadIdx.x;
    const float* st = g_stats + b * 64;
    const double* sd = g_statsd + b * 16;
    const float* vb = g_vert0 + (size_t)b * D3;
    float* ob = out + (size_t)b * OUTROWS * 3;

    if (r < 3500) {
        double vx = (double)vb[r * 3], vy = (double)vb[r * 3 + 1], vz = (double)vb[r * 3 + 2];
        double wx = vx - sd[13], wy = vy - sd[14], wz = vz - sd[15];
        double sc = sd[9];
        double ox = (wx * sd[0] + wy * sd[3] + wz * sd[6]) * sc + sd[10];
        double oy = (wx * sd[1] + wy * sd[4] + wz * sd[7]) * sc + sd[11];
        double oz = (wx * sd[2] + wy * sd[5] + wz * sd[8]) * sc + sd[12];
        ob[r * 3] = (float)ox; ob[r * 3 + 1] = (float)oy; ob[r * 3 + 2] = (float)oz;

        const float* C = cam + b * 12;
        double p0 = (double)C[0] * ox + (double)C[1] * oy + (double)C[2] * oz + (double)C[3];
        double p1 = (double)C[4] * ox + (double)C[5] * oy + (double)C[6] * oz + (double)C[7];
        double p2 = (double)C[8] * ox + (double)C[9] * oy + (double)C[10] * oz + (double)C[11];
        double zs = (p2 >= 0.0 ? 1.0 : -1.0) * fmax(fabs(p2), 0.001);
        size_t o2 = (size_t)(3500 + r) * 3;
        ob[o2] = __fdiv_rn((float)p0, (float)zs);
        ob[o2 + 1] = __fdiv_rn((float)p1, (float)zs);
        ob[o2 + 2] = (float)p2;
    } else if (r < 3568) {
        int i = r - 3500;
        int vi = mlm[i];
        double vx = (double)vb[vi * 3], vy = (double)vb[vi * 3 + 1], vz = (double)vb[vi * 3 + 2];
        double wx = vx - sd[13], wy = vy - sd[14], wz = vz - sd[15];
        double sc = sd[9];
        size_t o = (size_t)(7000 + i) * 3;
        ob[o]     = (float)((wx * sd[0] + wy * sd[3] + wz * sd[6]) * sc + sd[10]);
        ob[o + 1] = (float)((wx * sd[1] + wy * sd[4] + wz * sd[7]) * sc + sd[11]);
        ob[o + 2] = (float)((wx * sd[2] + wy * sd[5] + wz * sd[8]) * sc + sd[12]);
    } else if (r < 3578) {
        int sidx = r - 3568;
        size_t o = (size_t)(7068 + sidx) * 3;
        ob[o] = st[16 + 3 * sidx];
        ob[o + 1] = st[17 + 3 * sidx];
        ob[o + 2] = st[18 + 3 * sidx];
    } else if (r == 3578) {
        float d = st[46];
        size_t o = (size_t)7078 * 3;
        ob[o] = d; ob[o + 1] = d; ob[o + 2] = d;
    }
}

// ---------------------------------------------------------------------------
// Launch
// ---------------------------------------------------------------------------
extern "C" void kernel_launch(void* const* d_in, const int* in_sizes, int n_in,
                              void* d_out, int out_size) {
    const float* x      = (const float*)d_in[0];
    const float* enc_W  = (const float*)d_in[1];
    const float* enc_b  = (const float*)d_in[2];
    const float* vtempl = (const float*)d_in[3];
    const float* basis  = (const float*)d_in[4];
    const float* cam    = (const float*)d_in[5];
    const int* landmarks = (const int*)d_in[6];
    const int* mlm       = (const int*)d_in[7];
    float* out = (float*)d_out;

    xsplit_kernel<<<(BATCH * KDIM / 4 + 255) / 256, 256>>>(x);
    gemm1_kernel<<<dim3(NBLK, KSPLIT), 256>>>(enc_W);
    reduce_kernel<<<BATCH, NPAD>>>(enc_b);
    shape_kernel<<<dim3(118, 2), 128>>>(basis, vtempl);
    stats_kernel<<<BATCH, 256>>>();
    geom_kernel<<<1, 64>>>(landmarks);
    out_kernel<<<dim3(28, BATCH), 128>>>(cam, mlm, out);
}